// round 4
// baseline (speedup 1.0000x reference)
#include <cuda_runtime.h>
#include <math.h>

// Problem constants: B=32, T=1024, D=256, H=256
#define BB 32
#define TT 1024
#define DD 256
#define HH 256
#define NPART 128            // partials per batch

// Scratch (device globals — no allocation allowed)
__device__ __align__(16) float g_partial[BB * NPART * DD];   // 4 MB
__device__ __align__(16) float g_W[BB * DD];
__device__ __align__(16) float g_bias[BB * DD];

// ---------------------------------------------------------------------------
// Kernel A: partial sums of x over T.
// grid = B*32 = 1024 blocks x 256 threads. Block (b, s): rows [s*32, s*32+32).
// Thread = (lt in [0,4), d4 in [0,64)): sums 8 rows {lt, lt+4, ...},
// 8 independent float4 loads, no block reduce (mlp absorbs 128 partials).
// ~55 warps/SM occupancy AND MLP=8 per thread.
// ---------------------------------------------------------------------------
__global__ __launch_bounds__(256) void reduce_c_kernel(const float4* __restrict__ x4) {
    int blk = blockIdx.x;
    int b = blk >> 5;            // / 32
    int s = blk & 31;            // % 32
    int d4 = threadIdx.x & 63;
    int lt = threadIdx.x >> 6;   // 0..3

    size_t base = ((size_t)b * TT + (size_t)s * 32 + lt) * 64 + d4;
    float4 acc = make_float4(0.f, 0.f, 0.f, 0.f);
#pragma unroll
    for (int i = 0; i < 8; i++) {
        float4 v = x4[base + (size_t)i * 4 * 64];
        acc.x += v.x; acc.y += v.y; acc.z += v.z; acc.w += v.w;
    }
    // partial index p = s*4 + lt  (0..127)
    reinterpret_cast<float4*>(g_partial)[((size_t)b * NPART + (s * 4 + lt)) * 64 + d4] = acc;
}

// ---------------------------------------------------------------------------
// Kernel B: per-batch MLPs, warp-per-output, float4 weight loads.
// grid = 2*B = 64 blocks (b, branch), 256 threads = 8 warps.
// ---------------------------------------------------------------------------
__device__ __forceinline__ float gelu_exact(float v) {
    return 0.5f * v * (1.0f + erff(v * 0.70710678118654752f));
}

__device__ __forceinline__ float dot4(float4 a, float4 b) {
    return fmaf(a.x, b.x, fmaf(a.y, b.y, fmaf(a.z, b.z, a.w * b.w)));
}

__global__ __launch_bounds__(256) void mlp_kernel(
        const int* __restrict__ len,
        const float* __restrict__ w1w, const float* __restrict__ w1b,
        const float* __restrict__ w2w, const float* __restrict__ w2b,
        const float* __restrict__ q1w, const float* __restrict__ q1b,
        const float* __restrict__ q2w, const float* __restrict__ q2b) {
    __shared__ __align__(16) float c_sh[DD];
    __shared__ __align__(16) float h_sh[HH];

    int b = blockIdx.x >> 1;
    int branch = blockIdx.x & 1;
    const float* m1w = branch ? q1w : w1w;
    const float* m1b = branch ? q1b : w1b;
    const float* m2w = branch ? q2w : w2w;
    const float* m2b = branch ? q2b : w2b;
    float* gout = branch ? g_bias : g_W;

    int j = threadIdx.x;
    // reduce 128 partials -> c (coalesced over j)
    {
        float s = 0.0f;
#pragma unroll 16
        for (int p = 0; p < NPART; p++)
            s += g_partial[((size_t)b * NPART + p) * DD + j];
        c_sh[j] = s / (float)len[b];
    }
    __syncthreads();

    int w = threadIdx.x >> 5;
    int lane = threadIdx.x & 31;
    const float4* c4 = reinterpret_cast<const float4*>(c_sh);
    const float4* h4 = reinterpret_cast<const float4*>(h_sh);

    // layer 1: h = gelu(c @ W1^T + b1); warp computes outputs [w*32, w*32+32)
#pragma unroll 8
    for (int jj = 0; jj < 32; jj++) {
        int o = w * 32 + jj;
        const float4* row = reinterpret_cast<const float4*>(m1w + (size_t)o * DD);
        float acc = dot4(c4[lane], row[lane]) + dot4(c4[lane + 32], row[lane + 32]);
#pragma unroll
        for (int off = 16; off > 0; off >>= 1)
            acc += __shfl_down_sync(0xFFFFFFFFu, acc, off);
        if (lane == 0) h_sh[o] = gelu_exact(acc + m1b[o]);
    }
    __syncthreads();

    // layer 2: out = h @ W2^T + b2
#pragma unroll 8
    for (int jj = 0; jj < 32; jj++) {
        int o = w * 32 + jj;
        const float4* row = reinterpret_cast<const float4*>(m2w + (size_t)o * HH);
        float acc = dot4(h4[lane], row[lane]) + dot4(h4[lane + 32], row[lane + 32]);
#pragma unroll
        for (int off = 16; off > 0; off >>= 1)
            acc += __shfl_down_sync(0xFFFFFFFFu, acc, off);
        if (lane == 0) gout[b * DD + o] = acc + m2b[o];
    }
}

// ---------------------------------------------------------------------------
// Kernel C: elementwise apply.
//   out[b,t,d] = t < L ? x*(1+W[b,d]) + (t==0)*bias[b,d] : 0
// grid = 2048 blocks x 256 threads; thread handles 4 float4 at stride 256.
// d4 is invariant per thread (i & 63 with stride-256 steps) -> W load hoisted.
// x load is skipped for t >= L (t warp-uniform), saving ~half the read BW.
// ---------------------------------------------------------------------------
__global__ __launch_bounds__(256) void apply_kernel(const float4* __restrict__ x4,
                                                    const int* __restrict__ len,
                                                    float4* __restrict__ out4) {
    size_t base = (size_t)blockIdx.x * 1024;
    int b = (int)(base >> 16);
    int L = __ldg(&len[b]);
    int d4 = (int)((base + threadIdx.x) & 63);      // invariant across k
    int t0 = (int)(((base + threadIdx.x) >> 6) & 1023);

    float4 wv = reinterpret_cast<const float4*>(g_W)[b * 64 + d4];

#pragma unroll
    for (int k = 0; k < 4; k++) {
        size_t i = base + threadIdx.x + (size_t)k * 256;
        int t = t0 + k * 4;                         // each k advances 4 t-rows

        float4 o;
        if (t < L) {
            float4 xv = x4[i];
            o.x = fmaf(xv.x, wv.x, xv.x);
            o.y = fmaf(xv.y, wv.y, xv.y);
            o.z = fmaf(xv.z, wv.z, xv.z);
            o.w = fmaf(xv.w, wv.w, xv.w);
            if (t == 0) {
                float4 bv = reinterpret_cast<const float4*>(g_bias)[b * 64 + d4];
                o.x += bv.x; o.y += bv.y; o.z += bv.z; o.w += bv.w;
            }
        } else {
            o = make_float4(0.f, 0.f, 0.f, 0.f);
        }
        __stcs(&out4[i], o);   // streaming store: don't evict x from L2
    }
}

// ---------------------------------------------------------------------------
extern "C" void kernel_launch(void* const* d_in, const int* in_sizes, int n_in,
                              void* d_out, int out_size) {
    const float* x     = (const float*)d_in[0];
    const int*   len_x = (const int*)d_in[1];
    const float* Ww1_w = (const float*)d_in[2];
    const float* Ww1_b = (const float*)d_in[3];
    const float* Ww2_w = (const float*)d_in[4];
    const float* Ww2_b = (const float*)d_in[5];
    const float* Wb1_w = (const float*)d_in[6];
    const float* Wb1_b = (const float*)d_in[7];
    const float* Wb2_w = (const float*)d_in[8];
    const float* Wb2_b = (const float*)d_in[9];
    float* out = (float*)d_out;

    reduce_c_kernel<<<BB * 32, 256>>>(reinterpret_cast<const float4*>(x));
    mlp_kernel<<<2 * BB, 256>>>(len_x, Ww1_w, Ww1_b, Ww2_w, Ww2_b,
                                Wb1_w, Wb1_b, Wb2_w, Wb2_b);
    apply_kernel<<<2048, 256>>>(reinterpret_cast<const float4*>(x), len_x,
                                reinterpret_cast<float4*>(out));
}